// round 7
// baseline (speedup 1.0000x reference)
#include <cuda_runtime.h>
#include <cuda_bf16.h>
#include <cstdint>

// Histogram_15126874816754:
//   out[b, (p>0), y, x] += |p|/STD  over N events, then clip at 1.0.
// Strategy:
//   - zero pass with evict_last stores (pins 59 MB image in L2)
//   - scatter with atom.add (returns old); threads seeing old+v>1 push the
//     pixel index to a small static overflow list -> full-image clip pass
//     replaced by a tiny cleanup. If the list ever overflows (never, for
//     this data), cleanup falls back to a full clip sweep: correctness is
//     unconditional.
//   - two dummy pre-kernels shift the scatter kernel into ncu's profiled
//     launch slot (position 4) for next-round visibility.

#define INV_STD_C  (1.0f / 20.0f)
#define CLIP_MAX_C 1.0f
#define OVF_CAP    (1 << 16)   // 64K entries, 256 KB static scratch

__device__ int g_ovf_count;
__device__ int g_ovf_idx[OVF_CAP];

__device__ __forceinline__ uint64_t make_evict_last_policy() {
    uint64_t pol;
    asm("createpolicy.fractional.L2::evict_last.b64 %0, 1.0;" : "=l"(pol));
    return pol;
}

// atomic add returning old value, with L2 evict_last hint
__device__ __forceinline__ float atom_add_f32_evict_last(float* p, float v, uint64_t pol) {
    float old;
    asm volatile(
        "atom.relaxed.gpu.global.L2::cache_hint.add.f32 %0, [%1], %2, %3;"
        : "=f"(old) : "l"(p), "f"(v), "l"(pol) : "memory");
    return old;
}

__device__ __forceinline__ void st_zero4_evict_last(float4* p, uint64_t pol) {
    const float z = 0.0f;
    asm volatile(
        "st.global.L2::cache_hint.v4.f32 [%0], {%1, %1, %1, %1}, %2;"
        :: "l"(p), "f"(z), "l"(pol) : "memory");
}

// no-op kernel: shifts ncu's profiled-launch position so scatter lands at #4
__global__ void hist_dummy_kernel() {}

// ---------------------------------------------------------------------------
// Zero pass (one float4 per thread; the L2 write path caps this pass, more
// ILP was measured neutral). Also resets the overflow counter.
// ---------------------------------------------------------------------------
__global__ void __launch_bounds__(256)
hist_zero_kernel(float* __restrict__ out, int n)
{
    const int n4 = n >> 2;
    const int i = blockIdx.x * blockDim.x + threadIdx.x;
    const uint64_t pol = make_evict_last_policy();

    if (i == 0) g_ovf_count = 0;

    if (i < n4) {
        st_zero4_evict_last(reinterpret_cast<float4*>(out) + i, pol);
    } else if (i == n4) {
        for (int k = n4 * 4; k < n; ++k) out[k] = 0.0f;
    }
}

// ---------------------------------------------------------------------------
// Scatter: 8 events/thread, streaming input loads, atom.add with overflow
// detection (sums are monotone non-decreasing, so any pixel ending >1 is
// caught by its final add).
// ---------------------------------------------------------------------------
__global__ void __launch_bounds__(256)
hist_scatter_kernel(const int4* __restrict__ xs,
                    const int4* __restrict__ ys,
                    const float4* __restrict__ ps,
                    const int4* __restrict__ bs,
                    const int* __restrict__ wp,
                    const int* __restrict__ hp,
                    float* __restrict__ out,
                    int n8)
{
    const int W = __ldg(wp);
    const int H = __ldg(hp);
    const uint64_t pol = make_evict_last_policy();

    const int i = blockIdx.x * blockDim.x + threadIdx.x;
    if (i >= n8) return;

    const int4   x0 = __ldcs(xs + 2 * i),  x1 = __ldcs(xs + 2 * i + 1);
    const int4   y0 = __ldcs(ys + 2 * i),  y1 = __ldcs(ys + 2 * i + 1);
    const float4 p0 = __ldcs(ps + 2 * i),  p1 = __ldcs(ps + 2 * i + 1);
    const int4   b0 = __ldcs(bs + 2 * i),  b1 = __ldcs(bs + 2 * i + 1);

#define SCATTER_ONE(xx, yy, pp, bb)                                          \
    {                                                                        \
        const int   pos = (pp) > 0.0f;                                       \
        const int   idx = (((bb) * 2 + pos) * H + (yy)) * W + (xx);          \
        const float val = fabsf(pp) * INV_STD_C;                             \
        const float old = atom_add_f32_evict_last(out + idx, val, pol);      \
        if (old + val > CLIP_MAX_C) {                                        \
            const int slot = atomicAdd(&g_ovf_count, 1);                     \
            if (slot < OVF_CAP) g_ovf_idx[slot] = idx;                       \
        }                                                                    \
    }

    SCATTER_ONE(x0.x, y0.x, p0.x, b0.x)
    SCATTER_ONE(x0.y, y0.y, p0.y, b0.y)
    SCATTER_ONE(x0.z, y0.z, p0.z, b0.z)
    SCATTER_ONE(x0.w, y0.w, p0.w, b0.w)
    SCATTER_ONE(x1.x, y1.x, p1.x, b1.x)
    SCATTER_ONE(x1.y, y1.y, p1.y, b1.y)
    SCATTER_ONE(x1.z, y1.z, p1.z, b1.z)
    SCATTER_ONE(x1.w, y1.w, p1.w, b1.w)
#undef SCATTER_ONE
}

__global__ void
hist_scatter_tail_kernel(const int* __restrict__ xs,
                         const int* __restrict__ ys,
                         const float* __restrict__ ps,
                         const int* __restrict__ bs,
                         const int* __restrict__ wp,
                         const int* __restrict__ hp,
                         float* __restrict__ out,
                         int start, int n)
{
    const int k = start + blockIdx.x * blockDim.x + threadIdx.x;
    if (k >= n) return;
    const int W = __ldg(wp);
    const int H = __ldg(hp);
    const float pk = ps[k];
    const int pos = pk > 0.0f;
    const int idx = ((bs[k] * 2 + pos) * H + ys[k]) * W + xs[k];
    const float val = fabsf(pk) * INV_STD_C;
    const float old = atomicAdd(out + idx, val);
    if (old + val > CLIP_MAX_C) {
        const int slot = atomicAdd(&g_ovf_count, 1);
        if (slot < OVF_CAP) g_ovf_idx[slot] = idx;
    }
}

// ---------------------------------------------------------------------------
// Cleanup: clip the recorded overflow pixels. If the list overflowed
// (count > OVF_CAP; never expected), fall back to a full clip sweep so the
// result is correct for ANY input.
// ---------------------------------------------------------------------------
__global__ void __launch_bounds__(256)
hist_cleanup_kernel(float* __restrict__ out, int n)
{
    const int c = g_ovf_count;
    const int stride = gridDim.x * blockDim.x;
    const int base = blockIdx.x * blockDim.x + threadIdx.x;

    if (c <= OVF_CAP) {
        for (int i = base; i < c; i += stride) {
            const int idx = g_ovf_idx[i];
            const float v = out[idx];
            if (v > CLIP_MAX_C) out[idx] = CLIP_MAX_C;
        }
    } else {
        // fallback: full clip (list was lossy)
        const int n4 = n >> 2;
        float4* o4 = reinterpret_cast<float4*>(out);
        for (int i = base; i < n4; i += stride) {
            float4 v = o4[i];
            if (v.x > CLIP_MAX_C || v.y > CLIP_MAX_C ||
                v.z > CLIP_MAX_C || v.w > CLIP_MAX_C) {
                v.x = fminf(v.x, CLIP_MAX_C);
                v.y = fminf(v.y, CLIP_MAX_C);
                v.z = fminf(v.z, CLIP_MAX_C);
                v.w = fminf(v.w, CLIP_MAX_C);
                o4[i] = v;
            }
        }
        if (base == 0)
            for (int k = n4 * 4; k < n; ++k)
                out[k] = fminf(out[k], CLIP_MAX_C);
    }
}

// ---------------------------------------------------------------------------
extern "C" void kernel_launch(void* const* d_in, const int* in_sizes, int n_in,
                              void* d_out, int out_size)
{
    const int*   xs = (const int*)  d_in[0];
    const int*   ys = (const int*)  d_in[1];
    const float* ps = (const float*)d_in[2];
    const int*   bs = (const int*)  d_in[3];
    const int*   wp = (const int*)  d_in[4];
    const int*   hp = (const int*)  d_in[5];

    float* out = (float*)d_out;
    const int n = in_sizes[0];

    // launch-position shims: put scatter at profiled slot #4
    hist_dummy_kernel<<<1, 32>>>();
    hist_dummy_kernel<<<1, 32>>>();

    // 1) zero image (+ reset overflow counter)
    {
        const int n4 = out_size >> 2;
        const int total_threads = n4 + ((out_size & 3) ? 1 : 0);
        const int blocks = (total_threads + 255) / 256;
        hist_zero_kernel<<<blocks, 256>>>(out, out_size);
    }

    // 2) scatter-add with overflow detection
    {
        const int n8 = n >> 3;
        if (n8 > 0) {
            const int blocks = (n8 + 255) / 256;
            hist_scatter_kernel<<<blocks, 256>>>(
                (const int4*)xs, (const int4*)ys, (const float4*)ps,
                (const int4*)bs, wp, hp, out, n8);
        }
        if (n & 7) {
            hist_scatter_tail_kernel<<<1, 32>>>(xs, ys, ps, bs, wp, hp,
                                                out, n & ~7, n);
        }
    }

    // 3) clip only overflowed pixels (expected: none; lossy-list fallback = full sweep)
    hist_cleanup_kernel<<<512, 256>>>(out, out_size);
}

// round 8
// speedup vs baseline: 1.0111x; 1.0111x over previous
#include <cuda_runtime.h>
#include <cuda_bf16.h>
#include <cstdint>

// Histogram_15126874816754:
//   out[b, (p>0), y, x] += |p|/STD  over N events, then clip at 1.0.
// Strategy:
//   - zero pass with evict_last stores (pins 59 MB image in L2)
//   - scatter: BATCHED atom.adds (all 8 issued back-to-back -> MLP=8, the
//     ~320cyc L2 round trip is overlapped once, not serialized 8x like R7),
//     then one branch-free overflow check. Pixels ending >1 are recorded
//     exactly (sums are monotone; the final add observes old+val>1).
//   - cleanup clips only recorded pixels (expected none); lossy-list
//     fallback does a full sweep so correctness is unconditional.
//   - two dummy pre-kernels keep scatter in ncu's profiled slot.

#define INV_STD_C  (1.0f / 20.0f)
#define CLIP_MAX_C 1.0f
#define OVF_CAP    (1 << 16)   // 64K entries, 256 KB static scratch

__device__ int g_ovf_count;
__device__ int g_ovf_idx[OVF_CAP];

__device__ __forceinline__ uint64_t make_evict_last_policy() {
    uint64_t pol;
    asm("createpolicy.fractional.L2::evict_last.b64 %0, 1.0;" : "=l"(pol));
    return pol;
}

__device__ __forceinline__ float atom_add_f32_evict_last(float* p, float v, uint64_t pol) {
    float old;
    asm volatile(
        "atom.relaxed.gpu.global.L2::cache_hint.add.f32 %0, [%1], %2, %3;"
        : "=f"(old) : "l"(p), "f"(v), "l"(pol) : "memory");
    return old;
}

__device__ __forceinline__ void st_zero4_evict_last(float4* p, uint64_t pol) {
    const float z = 0.0f;
    asm volatile(
        "st.global.L2::cache_hint.v4.f32 [%0], {%1, %1, %1, %1}, %2;"
        :: "l"(p), "f"(z), "l"(pol) : "memory");
}

// no-op kernel: keeps scatter at ncu's profiled launch slot
__global__ void hist_dummy_kernel() {}

// ---------------------------------------------------------------------------
// Zero pass. Also resets the overflow counter.
// ---------------------------------------------------------------------------
__global__ void __launch_bounds__(256)
hist_zero_kernel(float* __restrict__ out, int n)
{
    const int n4 = n >> 2;
    const int i = blockIdx.x * blockDim.x + threadIdx.x;
    const uint64_t pol = make_evict_last_policy();

    if (i == 0) g_ovf_count = 0;

    if (i < n4) {
        st_zero4_evict_last(reinterpret_cast<float4*>(out) + i, pol);
    } else if (i == n4) {
        for (int k = n4 * 4; k < n; ++k) out[k] = 0.0f;
    }
}

// ---------------------------------------------------------------------------
// Scatter: 8 events/thread. Phase 1: compute all idx/val. Phase 2: issue all
// 8 atom.adds with NO consumers in between (MLP=8). Phase 3: one combined
// overflow check; the push path is cold.
// ---------------------------------------------------------------------------
__global__ void __launch_bounds__(256)
hist_scatter_kernel(const int4* __restrict__ xs,
                    const int4* __restrict__ ys,
                    const float4* __restrict__ ps,
                    const int4* __restrict__ bs,
                    const int* __restrict__ wp,
                    const int* __restrict__ hp,
                    float* __restrict__ out,
                    int n8)
{
    const int W = __ldg(wp);
    const int H = __ldg(hp);
    const uint64_t pol = make_evict_last_policy();

    const int i = blockIdx.x * blockDim.x + threadIdx.x;
    if (i >= n8) return;

    const int4   x0 = __ldcs(xs + 2 * i),  x1 = __ldcs(xs + 2 * i + 1);
    const int4   y0 = __ldcs(ys + 2 * i),  y1 = __ldcs(ys + 2 * i + 1);
    const float4 p0 = __ldcs(ps + 2 * i),  p1 = __ldcs(ps + 2 * i + 1);
    const int4   b0 = __ldcs(bs + 2 * i),  b1 = __ldcs(bs + 2 * i + 1);

    int   idx[8];
    float val[8];
    {
        const int xa[8] = {x0.x, x0.y, x0.z, x0.w, x1.x, x1.y, x1.z, x1.w};
        const int ya[8] = {y0.x, y0.y, y0.z, y0.w, y1.x, y1.y, y1.z, y1.w};
        const float pa[8] = {p0.x, p0.y, p0.z, p0.w, p1.x, p1.y, p1.z, p1.w};
        const int ba[8] = {b0.x, b0.y, b0.z, b0.w, b1.x, b1.y, b1.z, b1.w};
#pragma unroll
        for (int j = 0; j < 8; ++j) {
            const int pos = pa[j] > 0.0f;
            idx[j] = ((ba[j] * 2 + pos) * H + ya[j]) * W + xa[j];
            val[j] = fabsf(pa[j]) * INV_STD_C;
        }
    }

    // Phase 2: all atoms issued back-to-back — no result consumed yet.
    float old[8];
#pragma unroll
    for (int j = 0; j < 8; ++j)
        old[j] = atom_add_f32_evict_last(out + idx[j], val[j], pol);

    // Phase 3: single combined check; push path is cold.
    float m = old[0] + val[0];
#pragma unroll
    for (int j = 1; j < 8; ++j)
        m = fmaxf(m, old[j] + val[j]);

    if (m > CLIP_MAX_C) {
#pragma unroll
        for (int j = 0; j < 8; ++j) {
            if (old[j] + val[j] > CLIP_MAX_C) {
                const int slot = atomicAdd(&g_ovf_count, 1);
                if (slot < OVF_CAP) g_ovf_idx[slot] = idx[j];
            }
        }
    }
}

__global__ void
hist_scatter_tail_kernel(const int* __restrict__ xs,
                         const int* __restrict__ ys,
                         const float* __restrict__ ps,
                         const int* __restrict__ bs,
                         const int* __restrict__ wp,
                         const int* __restrict__ hp,
                         float* __restrict__ out,
                         int start, int n)
{
    const int k = start + blockIdx.x * blockDim.x + threadIdx.x;
    if (k >= n) return;
    const int W = __ldg(wp);
    const int H = __ldg(hp);
    const float pk = ps[k];
    const int pos = pk > 0.0f;
    const int idx = ((bs[k] * 2 + pos) * H + ys[k]) * W + xs[k];
    const float val = fabsf(pk) * INV_STD_C;
    const float old = atomicAdd(out + idx, val);
    if (old + val > CLIP_MAX_C) {
        const int slot = atomicAdd(&g_ovf_count, 1);
        if (slot < OVF_CAP) g_ovf_idx[slot] = idx;
    }
}

// ---------------------------------------------------------------------------
// Cleanup: clip recorded overflow pixels; full-sweep fallback if the list
// was lossy (count > OVF_CAP; never expected).
// ---------------------------------------------------------------------------
__global__ void __launch_bounds__(256)
hist_cleanup_kernel(float* __restrict__ out, int n)
{
    const int c = g_ovf_count;
    const int stride = gridDim.x * blockDim.x;
    const int base = blockIdx.x * blockDim.x + threadIdx.x;

    if (c <= OVF_CAP) {
        for (int i = base; i < c; i += stride) {
            const int idx = g_ovf_idx[i];
            const float v = out[idx];
            if (v > CLIP_MAX_C) out[idx] = CLIP_MAX_C;
        }
    } else {
        const int n4 = n >> 2;
        float4* o4 = reinterpret_cast<float4*>(out);
        for (int i = base; i < n4; i += stride) {
            float4 v = o4[i];
            if (v.x > CLIP_MAX_C || v.y > CLIP_MAX_C ||
                v.z > CLIP_MAX_C || v.w > CLIP_MAX_C) {
                v.x = fminf(v.x, CLIP_MAX_C);
                v.y = fminf(v.y, CLIP_MAX_C);
                v.z = fminf(v.z, CLIP_MAX_C);
                v.w = fminf(v.w, CLIP_MAX_C);
                o4[i] = v;
            }
        }
        if (base == 0)
            for (int k = n4 * 4; k < n; ++k)
                out[k] = fminf(out[k], CLIP_MAX_C);
    }
}

// ---------------------------------------------------------------------------
extern "C" void kernel_launch(void* const* d_in, const int* in_sizes, int n_in,
                              void* d_out, int out_size)
{
    const int*   xs = (const int*)  d_in[0];
    const int*   ys = (const int*)  d_in[1];
    const float* ps = (const float*)d_in[2];
    const int*   bs = (const int*)  d_in[3];
    const int*   wp = (const int*)  d_in[4];
    const int*   hp = (const int*)  d_in[5];

    float* out = (float*)d_out;
    const int n = in_sizes[0];

    // shims: keep scatter at ncu's profiled slot
    hist_dummy_kernel<<<1, 32>>>();
    hist_dummy_kernel<<<1, 32>>>();

    // 1) zero image (+ reset overflow counter)
    {
        const int n4 = out_size >> 2;
        const int total_threads = n4 + ((out_size & 3) ? 1 : 0);
        const int blocks = (total_threads + 255) / 256;
        hist_zero_kernel<<<blocks, 256>>>(out, out_size);
    }

    // 2) scatter-add, batched atoms
    {
        const int n8 = n >> 3;
        if (n8 > 0) {
            const int blocks = (n8 + 255) / 256;
            hist_scatter_kernel<<<blocks, 256>>>(
                (const int4*)xs, (const int4*)ys, (const float4*)ps,
                (const int4*)bs, wp, hp, out, n8);
        }
        if (n & 7) {
            hist_scatter_tail_kernel<<<1, 32>>>(xs, ys, ps, bs, wp, hp,
                                                out, n & ~7, n);
        }
    }

    // 3) clip only overflowed pixels (expected none)
    hist_cleanup_kernel<<<128, 256>>>(out, out_size);
}

// round 9
// speedup vs baseline: 1.2340x; 1.2204x over previous
#include <cuda_runtime.h>
#include <cuda_bf16.h>
#include <cstdint>

// Histogram_15126874816754:
//   out[b, (p>0), y, x] += |p|/STD  over N events, then clip at 1.0.
// R8 verdict: value-returning atom.add is ~60% slower than red regardless of
// batching -> overflow-list clip elimination abandoned. Back to the proven
// structure: evict_last zero -> red scatter (__ldcs inputs) -> clip pass,
// with the clip pass tuned (L2-resident reads, conditional stores).

#define INV_STD_C  (1.0f / 20.0f)
#define CLIP_MAX_C 1.0f

__device__ __forceinline__ uint64_t make_evict_last_policy() {
    uint64_t pol;
    asm("createpolicy.fractional.L2::evict_last.b64 %0, 1.0;" : "=l"(pol));
    return pol;
}

// fire-and-forget RED with L2 evict_last hint (keeps image resident)
__device__ __forceinline__ void red_add_f32_evict_last(float* p, float v, uint64_t pol) {
    asm volatile(
        "red.relaxed.gpu.global.L2::cache_hint.add.f32 [%0], %1, %2;"
        :: "l"(p), "f"(v), "l"(pol) : "memory");
}

__device__ __forceinline__ void st_zero4_evict_last(float4* p, uint64_t pol) {
    const float z = 0.0f;
    asm volatile(
        "st.global.L2::cache_hint.v4.f32 [%0], {%1, %1, %1, %1}, %2;"
        :: "l"(p), "f"(z), "l"(pol) : "memory");
}

// no-op kernel: keeps scatter at ncu's profiled launch slot (#4)
__global__ void hist_dummy_kernel() {}

// ---------------------------------------------------------------------------
// Zero pass: one float4/thread, evict_last stores (pins image in L2).
// The L2 write path caps this pass; more ILP measured neutral (R4).
// ---------------------------------------------------------------------------
__global__ void __launch_bounds__(256)
hist_zero_kernel(float* __restrict__ out, int n)
{
    const int n4 = n >> 2;
    const int i = blockIdx.x * blockDim.x + threadIdx.x;
    const uint64_t pol = make_evict_last_policy();

    if (i < n4) {
        st_zero4_evict_last(reinterpret_cast<float4*>(out) + i, pol);
    } else if (i == n4) {
        for (int k = n4 * 4; k < n; ++k) out[k] = 0.0f;
    }
}

// ---------------------------------------------------------------------------
// Scatter: 8 events/thread, front-batched __ldcs input loads (evict-first),
// RED.E.ADD.F32 with evict_last (no return value -> fast path, R3-proven).
// ---------------------------------------------------------------------------
__global__ void __launch_bounds__(256)
hist_scatter_kernel(const int4* __restrict__ xs,
                    const int4* __restrict__ ys,
                    const float4* __restrict__ ps,
                    const int4* __restrict__ bs,
                    const int* __restrict__ wp,
                    const int* __restrict__ hp,
                    float* __restrict__ out,
                    int n8)
{
    const int W = __ldg(wp);
    const int H = __ldg(hp);
    const uint64_t pol = make_evict_last_policy();

    const int i = blockIdx.x * blockDim.x + threadIdx.x;
    if (i >= n8) return;

    const int4   x0 = __ldcs(xs + 2 * i),  x1 = __ldcs(xs + 2 * i + 1);
    const int4   y0 = __ldcs(ys + 2 * i),  y1 = __ldcs(ys + 2 * i + 1);
    const float4 p0 = __ldcs(ps + 2 * i),  p1 = __ldcs(ps + 2 * i + 1);
    const int4   b0 = __ldcs(bs + 2 * i),  b1 = __ldcs(bs + 2 * i + 1);

#define SCATTER_ONE(xx, yy, pp, bb)                                        \
    {                                                                      \
        const int pos = (pp) > 0.0f;                                       \
        const int idx = (((bb) * 2 + pos) * H + (yy)) * W + (xx);          \
        red_add_f32_evict_last(out + idx, fabsf(pp) * INV_STD_C, pol);     \
    }

    SCATTER_ONE(x0.x, y0.x, p0.x, b0.x)
    SCATTER_ONE(x0.y, y0.y, p0.y, b0.y)
    SCATTER_ONE(x0.z, y0.z, p0.z, b0.z)
    SCATTER_ONE(x0.w, y0.w, p0.w, b0.w)
    SCATTER_ONE(x1.x, y1.x, p1.x, b1.x)
    SCATTER_ONE(x1.y, y1.y, p1.y, b1.y)
    SCATTER_ONE(x1.z, y1.z, p1.z, b1.z)
    SCATTER_ONE(x1.w, y1.w, p1.w, b1.w)
#undef SCATTER_ONE
}

__global__ void
hist_scatter_tail_kernel(const int* __restrict__ xs,
                         const int* __restrict__ ys,
                         const float* __restrict__ ps,
                         const int* __restrict__ bs,
                         const int* __restrict__ wp,
                         const int* __restrict__ hp,
                         float* __restrict__ out,
                         int start, int n)
{
    const int k = start + blockIdx.x * blockDim.x + threadIdx.x;
    if (k >= n) return;
    const int W = __ldg(wp);
    const int H = __ldg(hp);
    const float pk = ps[k];
    const int pos = pk > 0.0f;
    const int idx = ((bs[k] * 2 + pos) * H + ys[k]) * W + xs[k];
    atomicAdd(out + idx, fabsf(pk) * INV_STD_C);
}

// ---------------------------------------------------------------------------
// Clip: grid-stride, 4 x float4 per iteration via __ldcg (L2-targeted; the
// image is pinned there). Store only when a component exceeds 1.0 (rare),
// so the write stream nearly vanishes.
// ---------------------------------------------------------------------------
__global__ void __launch_bounds__(256)
hist_clip_kernel(float* __restrict__ out, int n)
{
    float4* o4 = reinterpret_cast<float4*>(out);
    const int n4 = n >> 2;

    const int stride = gridDim.x * blockDim.x;
    const int chunk  = stride * 4;
    const int base   = blockIdx.x * blockDim.x + threadIdx.x;

    int i = base;
    for (; i + 3 * stride < n4; i += chunk) {
        float4 v[4];
#pragma unroll
        for (int j = 0; j < 4; ++j)
            v[j] = __ldcg(o4 + i + j * stride);
#pragma unroll
        for (int j = 0; j < 4; ++j) {
            if (v[j].x > CLIP_MAX_C || v[j].y > CLIP_MAX_C ||
                v[j].z > CLIP_MAX_C || v[j].w > CLIP_MAX_C) {
                float4 w = v[j];
                w.x = fminf(w.x, CLIP_MAX_C);
                w.y = fminf(w.y, CLIP_MAX_C);
                w.z = fminf(w.z, CLIP_MAX_C);
                w.w = fminf(w.w, CLIP_MAX_C);
                o4[i + j * stride] = w;
            }
        }
    }
    for (; i < n4; i += stride) {
        float4 v = __ldcg(o4 + i);
        if (v.x > CLIP_MAX_C || v.y > CLIP_MAX_C ||
            v.z > CLIP_MAX_C || v.w > CLIP_MAX_C) {
            v.x = fminf(v.x, CLIP_MAX_C);
            v.y = fminf(v.y, CLIP_MAX_C);
            v.z = fminf(v.z, CLIP_MAX_C);
            v.w = fminf(v.w, CLIP_MAX_C);
            o4[i] = v;
        }
    }
    if (base == 0) {
        for (int k = n4 * 4; k < n; ++k) {
            const float v = out[k];
            if (v > CLIP_MAX_C) out[k] = CLIP_MAX_C;
        }
    }
}

// ---------------------------------------------------------------------------
extern "C" void kernel_launch(void* const* d_in, const int* in_sizes, int n_in,
                              void* d_out, int out_size)
{
    const int*   xs = (const int*)  d_in[0];
    const int*   ys = (const int*)  d_in[1];
    const float* ps = (const float*)d_in[2];
    const int*   bs = (const int*)  d_in[3];
    const int*   wp = (const int*)  d_in[4];
    const int*   hp = (const int*)  d_in[5];

    float* out = (float*)d_out;
    const int n = in_sizes[0];

    // shims: keep scatter at ncu's profiled slot (#4)
    hist_dummy_kernel<<<1, 32>>>();
    hist_dummy_kernel<<<1, 32>>>();

    // 1) zero image (evict_last -> L2-resident)
    {
        const int n4 = out_size >> 2;
        const int total_threads = n4 + ((out_size & 3) ? 1 : 0);
        const int blocks = (total_threads + 255) / 256;
        hist_zero_kernel<<<blocks, 256>>>(out, out_size);
    }

    // 2) scatter-add (red, 8 events/thread)
    {
        const int n8 = n >> 3;
        if (n8 > 0) {
            const int blocks = (n8 + 255) / 256;
            hist_scatter_kernel<<<blocks, 256>>>(
                (const int4*)xs, (const int4*)ys, (const float4*)ps,
                (const int4*)bs, wp, hp, out, n8);
        }
        if (n & 7) {
            hist_scatter_tail_kernel<<<1, 32>>>(xs, ys, ps, bs, wp, hp,
                                                out, n & ~7, n);
        }
    }

    // 3) clip (grid-stride, conditional store)
    hist_clip_kernel<<<2048, 256>>>(out, out_size);
}

// round 10
// speedup vs baseline: 1.2682x; 1.0278x over previous
#include <cuda_runtime.h>
#include <cuda_bf16.h>
#include <cstdint>

// Histogram_15126874816754:
//   out[b, (p>0), y, x] += |p|/STD  over N events, then clip at 1.0.
// Settled structure (at the uncoalesced-atomic wavefront floor):
//   zero (evict_last stores, pins image in L2)
//   -> red scatter (__ldcs streaming inputs, evict_last REDs)
//   -> clip (L2-resident reads, conditional stores).
// R7/R8 proved value-returning atomics are ~60% slower than red; R9 profile
// confirmed scatter is at the ~2cyc/lane divergent-atomic L1tex floor.

#define INV_STD_C  (1.0f / 20.0f)
#define CLIP_MAX_C 1.0f

__device__ __forceinline__ uint64_t make_evict_last_policy() {
    uint64_t pol;
    asm("createpolicy.fractional.L2::evict_last.b64 %0, 1.0;" : "=l"(pol));
    return pol;
}

// fire-and-forget RED with L2 evict_last hint (keeps image resident)
__device__ __forceinline__ void red_add_f32_evict_last(float* p, float v, uint64_t pol) {
    asm volatile(
        "red.relaxed.gpu.global.L2::cache_hint.add.f32 [%0], %1, %2;"
        :: "l"(p), "f"(v), "l"(pol) : "memory");
}

__device__ __forceinline__ void st_zero4_evict_last(float4* p, uint64_t pol) {
    const float z = 0.0f;
    asm volatile(
        "st.global.L2::cache_hint.v4.f32 [%0], {%1, %1, %1, %1}, %2;"
        :: "l"(p), "f"(z), "l"(pol) : "memory");
}

// ---------------------------------------------------------------------------
// Zero pass: one float4/thread, evict_last stores. L2 write path caps this.
// ---------------------------------------------------------------------------
__global__ void __launch_bounds__(256)
hist_zero_kernel(float* __restrict__ out, int n)
{
    const int n4 = n >> 2;
    const int i = blockIdx.x * blockDim.x + threadIdx.x;
    const uint64_t pol = make_evict_last_policy();

    if (i < n4) {
        st_zero4_evict_last(reinterpret_cast<float4*>(out) + i, pol);
    } else if (i == n4) {
        for (int k = n4 * 4; k < n; ++k) out[k] = 0.0f;
    }
}

// ---------------------------------------------------------------------------
// Scatter: 8 events/thread, front-batched __ldcs input loads (evict-first),
// RED.E.ADD.F32 with evict_last. At the divergent-atomic wavefront floor.
// ---------------------------------------------------------------------------
__global__ void __launch_bounds__(256)
hist_scatter_kernel(const int4* __restrict__ xs,
                    const int4* __restrict__ ys,
                    const float4* __restrict__ ps,
                    const int4* __restrict__ bs,
                    const int* __restrict__ wp,
                    const int* __restrict__ hp,
                    float* __restrict__ out,
                    int n8)
{
    const int W = __ldg(wp);
    const int H = __ldg(hp);
    const uint64_t pol = make_evict_last_policy();

    const int i = blockIdx.x * blockDim.x + threadIdx.x;
    if (i >= n8) return;

    const int4   x0 = __ldcs(xs + 2 * i),  x1 = __ldcs(xs + 2 * i + 1);
    const int4   y0 = __ldcs(ys + 2 * i),  y1 = __ldcs(ys + 2 * i + 1);
    const float4 p0 = __ldcs(ps + 2 * i),  p1 = __ldcs(ps + 2 * i + 1);
    const int4   b0 = __ldcs(bs + 2 * i),  b1 = __ldcs(bs + 2 * i + 1);

#define SCATTER_ONE(xx, yy, pp, bb)                                        \
    {                                                                      \
        const int pos = (pp) > 0.0f;                                       \
        const int idx = (((bb) * 2 + pos) * H + (yy)) * W + (xx);          \
        red_add_f32_evict_last(out + idx, fabsf(pp) * INV_STD_C, pol);     \
    }

    SCATTER_ONE(x0.x, y0.x, p0.x, b0.x)
    SCATTER_ONE(x0.y, y0.y, p0.y, b0.y)
    SCATTER_ONE(x0.z, y0.z, p0.z, b0.z)
    SCATTER_ONE(x0.w, y0.w, p0.w, b0.w)
    SCATTER_ONE(x1.x, y1.x, p1.x, b1.x)
    SCATTER_ONE(x1.y, y1.y, p1.y, b1.y)
    SCATTER_ONE(x1.z, y1.z, p1.z, b1.z)
    SCATTER_ONE(x1.w, y1.w, p1.w, b1.w)
#undef SCATTER_ONE
}

__global__ void
hist_scatter_tail_kernel(const int* __restrict__ xs,
                         const int* __restrict__ ys,
                         const float* __restrict__ ps,
                         const int* __restrict__ bs,
                         const int* __restrict__ wp,
                         const int* __restrict__ hp,
                         float* __restrict__ out,
                         int start, int n)
{
    const int k = start + blockIdx.x * blockDim.x + threadIdx.x;
    if (k >= n) return;
    const int W = __ldg(wp);
    const int H = __ldg(hp);
    const float pk = ps[k];
    const int pos = pk > 0.0f;
    const int idx = ((bs[k] * 2 + pos) * H + ys[k]) * W + xs[k];
    atomicAdd(out + idx, fabsf(pk) * INV_STD_C);
}

// ---------------------------------------------------------------------------
// Clip: one float4/thread (R3 shape), __ldcg reads (image is L2-pinned),
// store only if a component exceeds 1.0 (rare) -> write stream ~vanishes.
// ---------------------------------------------------------------------------
__global__ void __launch_bounds__(256)
hist_clip_kernel(float* __restrict__ out, int n)
{
    const int n4 = n >> 2;
    const int i = blockIdx.x * blockDim.x + threadIdx.x;

    if (i < n4) {
        float4* o4 = reinterpret_cast<float4*>(out);
        float4 v = __ldcg(o4 + i);
        if (v.x > CLIP_MAX_C || v.y > CLIP_MAX_C ||
            v.z > CLIP_MAX_C || v.w > CLIP_MAX_C) {
            v.x = fminf(v.x, CLIP_MAX_C);
            v.y = fminf(v.y, CLIP_MAX_C);
            v.z = fminf(v.z, CLIP_MAX_C);
            v.w = fminf(v.w, CLIP_MAX_C);
            o4[i] = v;
        }
    } else if (i == n4) {
        for (int k = n4 * 4; k < n; ++k) {
            const float v = out[k];
            if (v > CLIP_MAX_C) out[k] = CLIP_MAX_C;
        }
    }
}

// ---------------------------------------------------------------------------
extern "C" void kernel_launch(void* const* d_in, const int* in_sizes, int n_in,
                              void* d_out, int out_size)
{
    const int*   xs = (const int*)  d_in[0];
    const int*   ys = (const int*)  d_in[1];
    const float* ps = (const float*)d_in[2];
    const int*   bs = (const int*)  d_in[3];
    const int*   wp = (const int*)  d_in[4];
    const int*   hp = (const int*)  d_in[5];

    float* out = (float*)d_out;
    const int n = in_sizes[0];

    // 1) zero image (evict_last -> L2-resident)
    {
        const int n4 = out_size >> 2;
        const int total_threads = n4 + ((out_size & 3) ? 1 : 0);
        const int blocks = (total_threads + 255) / 256;
        hist_zero_kernel<<<blocks, 256>>>(out, out_size);
    }

    // 2) scatter-add (red, 8 events/thread)
    {
        const int n8 = n >> 3;
        if (n8 > 0) {
            const int blocks = (n8 + 255) / 256;
            hist_scatter_kernel<<<blocks, 256>>>(
                (const int4*)xs, (const int4*)ys, (const float4*)ps,
                (const int4*)bs, wp, hp, out, n8);
        }
        if (n & 7) {
            hist_scatter_tail_kernel<<<1, 32>>>(xs, ys, ps, bs, wp, hp,
                                                out, n & ~7, n);
        }
    }

    // 3) clip (conditional store)
    {
        const int n4 = out_size >> 2;
        const int total_threads = n4 + ((out_size & 3) ? 1 : 0);
        const int blocks = (total_threads + 255) / 256;
        hist_clip_kernel<<<blocks, 256>>>(out, out_size);
    }
}